// round 16
// baseline (speedup 1.0000x reference)
#include <cuda_runtime.h>
#include <cuda_bf16.h>
#include <stdint.h>

#define B_DIM 4
#define T_DIM 4096
#define C_DIM 1024
#define H_DIM 64
#define QTILE 128
#define KT64  64
#define GRID_W 296
#define NITEMS 576

// ---- device scratch (no cudaMalloc allowed) ----
__device__ __align__(16) __nv_bfloat16 g_wh[3 * C_DIM * H_DIM];
__device__ __align__(16) __nv_bfloat16 g_wl[3 * C_DIM * H_DIM];
__device__ __align__(16) __nv_bfloat16 g_Qh[B_DIM * T_DIM * H_DIM];
__device__ __align__(16) __nv_bfloat16 g_Ql[B_DIM * T_DIM * H_DIM];
__device__ __align__(16) __nv_bfloat16 g_Kh[B_DIM * T_DIM * H_DIM];
__device__ __align__(16) __nv_bfloat16 g_Kl[B_DIM * T_DIM * H_DIM];
__device__ __align__(16) __nv_bfloat16 g_VTh[B_DIM * H_DIM * T_DIM];  // [b][d][t]
__device__ __align__(16) __nv_bfloat16 g_VTl[B_DIM * H_DIM * T_DIM];
__device__ __align__(16) float  g_Op[8 * B_DIM * T_DIM * H_DIM];      // [p][b][t][d]
__device__ __align__(16) float2 g_ML[8 * B_DIM * T_DIM];              // [p][b][t]

#define Q_SCALE 0.04508422002778f   // 1/sqrt(1024) * log2(e)

__device__ __forceinline__ uint32_t smem_u32(const void* p) {
    uint32_t a;
    asm("{ .reg .u64 t; cvta.to.shared.u64 t, %1; cvt.u32.u64 %0, t; }"
        : "=r"(a) : "l"(p));
    return a;
}
__device__ __forceinline__ float ex2f(float x) {
    float y; asm("ex2.approx.ftz.f32 %0, %1;" : "=f"(y) : "f"(x)); return y;
}
__device__ __forceinline__ uint32_t pack_bf16(float a, float b) {
    __nv_bfloat162 t = __floats2bfloat162_rn(a, b);
    return *reinterpret_cast<uint32_t*>(&t);
}
__device__ __forceinline__ float bf_hi(float v) {
    return __bfloat162float(__float2bfloat16(v));
}
__device__ __forceinline__ void ldsm_x4(uint32_t& r0, uint32_t& r1,
                                        uint32_t& r2, uint32_t& r3, uint32_t a) {
    asm volatile("ldmatrix.sync.aligned.m8n8.x4.shared.b16 {%0,%1,%2,%3}, [%4];"
                 : "=r"(r0), "=r"(r1), "=r"(r2), "=r"(r3) : "r"(a));
}
__device__ __forceinline__ void ldsm_x4_t(uint32_t& r0, uint32_t& r1,
                                          uint32_t& r2, uint32_t& r3, uint32_t a) {
    asm volatile("ldmatrix.sync.aligned.m8n8.x4.trans.shared.b16 {%0,%1,%2,%3}, [%4];"
                 : "=r"(r0), "=r"(r1), "=r"(r2), "=r"(r3) : "r"(a));
}
__device__ __forceinline__ void mma16816(float* c, const uint32_t* a,
                                         uint32_t b0, uint32_t b1) {
    asm volatile("mma.sync.aligned.m16n8k16.row.col.f32.bf16.bf16.f32 "
                 "{%0,%1,%2,%3}, {%4,%5,%6,%7}, {%8,%9}, {%0,%1,%2,%3};"
                 : "+f"(c[0]), "+f"(c[1]), "+f"(c[2]), "+f"(c[3])
                 : "r"(a[0]), "r"(a[1]), "r"(a[2]), "r"(a[3]), "r"(b0), "r"(b1));
}
__device__ __forceinline__ void cpa16(uint32_t s, const void* g) {
    asm volatile("cp.async.cg.shared.global [%0], [%1], 16;" :: "r"(s), "l"(g) : "memory");
}
#define CP_COMMIT asm volatile("cp.async.commit_group;" ::: "memory")
#define CP_WAIT1  asm volatile("cp.async.wait_group 1;" ::: "memory")
#define CP_WAIT0  asm volatile("cp.async.wait_group 0;" ::: "memory")

// ---------------------------------------------------------------------------
// Split W (3 x 1024 x 64) into bf16 hi/lo. grid 192 x 256.
// ---------------------------------------------------------------------------
__global__ __launch_bounds__(256) void splitw_kernel(
    const float* __restrict__ Wq, const float* __restrict__ Wk,
    const float* __restrict__ Wv)
{
    int idx = blockIdx.x * 256 + threadIdx.x;
    int m = idx >> 14;
    int rem = idx & 16383;
    const float* W = (m == 0) ? Wq : (m == 1) ? Wk : Wv;
    float4 v = ((const float4*)W)[rem];
    float h0 = bf_hi(v.x), h1 = bf_hi(v.y), h2 = bf_hi(v.z), h3 = bf_hi(v.w);
    ((uint2*)g_wh)[idx] = make_uint2(pack_bf16(h0, h1), pack_bf16(h2, h3));
    ((uint2*)g_wl)[idx] = make_uint2(pack_bf16(v.x - h0, v.y - h1),
                                     pack_bf16(v.z - h2, v.w - h3));
}

// ---------------------------------------------------------------------------
// QKV projection (round-13 fused design): fp32 x staged via cp.async, split to
// bf16 in-kernel ONCE, all 3 matrices per CTA. Grid 128, block 256.
// ---------------------------------------------------------------------------
#define PXF 0
#define PXF_SZ (128 * 272)            // 34816 per stage (fp32 x, 272B stride)
#define PXH (2 * PXF_SZ)              // 69632 (bf16 hi, 144B stride)
#define PXL (PXH + 18432)             // 88064
#define PW  (PXL + 18432)             // 106496
#define PW_SZ 51200                   // per stage: WH 25600 + WL 25600
#define PSM_TOTAL (PW + 2 * PW_SZ)    // 208896

__global__ __launch_bounds__(256) void proj_kernel(const float* __restrict__ x)
{
    extern __shared__ char smem[];
    const uint32_t sb = smem_u32(smem);
    const int tid  = threadIdx.x;
    const int lane = tid & 31;
    const int w    = tid >> 5;
    const int gquad = lane >> 2;
    const int tql   = lane & 3;
    const int lr    = lane & 7;
    const uint32_t kofs = (uint32_t)(((lane >> 3) & 1) << 3);
    const uint32_t nofs = (uint32_t)((lane >> 4) << 3);

    const int row0 = blockIdx.x * 128;
    const float* xsrc = x + (size_t)row0 * C_DIM;

    auto load_stage = [&](int kc, int st) {
        uint32_t xf = sb + PXF + st * PXF_SZ;
#pragma unroll
        for (int it = 0; it < 8; it++) {
            int idx = tid + it * 256;          // 2048 float4
            int row = idx >> 4, seg = idx & 15;
            cpa16(xf + row * 272 + seg * 16, xsrc + (size_t)row * C_DIM + kc * 64 + seg * 4);
        }
        uint32_t wb = sb + PW + st * PW_SZ;
#pragma unroll
        for (int it = 0; it < 6; it++) {
            int idx = tid + it * 256;          // 1536
            int kr = idx / 24, s24 = idx - kr * 24;
            int m = s24 >> 3, seg = s24 & 7;
            size_t gsrc = ((size_t)m * C_DIM + kc * 64 + kr) * H_DIM + seg * 8;
            cpa16(wb + kr * 400 + s24 * 16, g_wh + gsrc);
            cpa16(wb + 25600 + kr * 400 + s24 * 16, g_wl + gsrc);
        }
    };

    load_stage(0, 0);
    CP_COMMIT;

    float s[24][4];
#pragma unroll
    for (int nb = 0; nb < 24; nb++)
#pragma unroll
        for (int e = 0; e < 4; e++) s[nb][e] = 0.f;

    const uint32_t a_row = 16 * w + (lane & 15);
    const uint32_t a_colb = (uint32_t)((lane >> 4) << 4);

    for (int kc = 0; kc < 16; kc++) {
        if (kc < 15) { load_stage(kc + 1, (kc + 1) & 1); CP_COMMIT; CP_WAIT1; }
        else         { CP_WAIT0; }
        __syncthreads();   // stage kc ready

        // convert fp32 x chunk -> split bf16 (single-buffered Xbf)
        {
            const char* xf = smem + PXF + (kc & 1) * PXF_SZ;
#pragma unroll
            for (int it = 0; it < 8; it++) {
                int idx = tid + it * 256;
                int row = idx >> 4, seg = idx & 15;
                float4 v = *(const float4*)(xf + row * 272 + seg * 16);
                float h0 = bf_hi(v.x), h1 = bf_hi(v.y), h2 = bf_hi(v.z), h3 = bf_hi(v.w);
                *(uint32_t*)(smem + PXH + row * 144 + seg * 8)     = pack_bf16(h0, h1);
                *(uint32_t*)(smem + PXH + row * 144 + seg * 8 + 4) = pack_bf16(h2, h3);
                *(uint32_t*)(smem + PXL + row * 144 + seg * 8)     = pack_bf16(v.x - h0, v.y - h1);
                *(uint32_t*)(smem + PXL + row * 144 + seg * 8 + 4) = pack_bf16(v.z - h2, v.w - h3);
            }
        }
        __syncthreads();   // Xbf visible

        const uint32_t wbase = sb + PW + (kc & 1) * PW_SZ;
#pragma unroll
        for (int ks = 0; ks < 4; ks++) {
            uint32_t ah[4], al[4];
            ldsm_x4(ah[0], ah[1], ah[2], ah[3], sb + PXH + a_row * 144 + ks * 32 + a_colb);
            ldsm_x4(al[0], al[1], al[2], al[3], sb + PXL + a_row * 144 + ks * 32 + a_colb);
            const uint32_t wrow = (uint32_t)(ks * 16) + kofs + lr;
#pragma unroll
            for (int np = 0; np < 12; np++) {
                uint32_t woff = wrow * 400 + (np * 16 + nofs) * 2;
                uint32_t h0, h1, h2, h3, l0, l1, l2, l3;
                ldsm_x4_t(h0, h1, h2, h3, wbase + woff);
                ldsm_x4_t(l0, l1, l2, l3, wbase + 25600 + woff);
                mma16816(s[2 * np], ah, h0, h1);
                mma16816(s[2 * np], ah, l0, l1);
                mma16816(s[2 * np], al, h0, h1);
                mma16816(s[2 * np + 1], ah, h2, h3);
                mma16816(s[2 * np + 1], ah, l2, l3);
                mma16816(s[2 * np + 1], al, h2, h3);
            }
        }
        // RACE FIX: next iteration's load_stage overwrites same-parity buffers
        // that lagging warps may still be reading. Barrier before next cp.async.
        __syncthreads();
    }

    // ---- epilogue ----
    const int ra = 16 * w + gquad;
    const int rb = ra + 8;
    const size_t ga = (size_t)(row0 + ra) * H_DIM;
    const size_t gb = (size_t)(row0 + rb) * H_DIM;

#pragma unroll
    for (int nb = 0; nb < 8; nb++) {   // Q (scaled)
        int col = 8 * nb + 2 * tql;
        float q0 = s[nb][0] * Q_SCALE, q1 = s[nb][1] * Q_SCALE;
        float q2 = s[nb][2] * Q_SCALE, q3 = s[nb][3] * Q_SCALE;
        float h0 = bf_hi(q0), h1 = bf_hi(q1), h2 = bf_hi(q2), h3 = bf_hi(q3);
        *(uint32_t*)&g_Qh[ga + col] = pack_bf16(h0, h1);
        *(uint32_t*)&g_Ql[ga + col] = pack_bf16(q0 - h0, q1 - h1);
        *(uint32_t*)&g_Qh[gb + col] = pack_bf16(h2, h3);
        *(uint32_t*)&g_Ql[gb + col] = pack_bf16(q2 - h2, q3 - h3);
    }
#pragma unroll
    for (int nb = 8; nb < 16; nb++) {  // K
        int col = 8 * (nb - 8) + 2 * tql;
        float k0 = s[nb][0], k1 = s[nb][1], k2 = s[nb][2], k3 = s[nb][3];
        float h0 = bf_hi(k0), h1 = bf_hi(k1), h2 = bf_hi(k2), h3 = bf_hi(k3);
        *(uint32_t*)&g_Kh[ga + col] = pack_bf16(h0, h1);
        *(uint32_t*)&g_Kl[ga + col] = pack_bf16(k0 - h0, k1 - h1);
        *(uint32_t*)&g_Kh[gb + col] = pack_bf16(h2, h3);
        *(uint32_t*)&g_Kl[gb + col] = pack_bf16(k2 - h2, k3 - h3);
    }
    // V transposed staging in the (now free) XF region.
    char* VSH = smem;              // 64 x 272B
    char* VSL = smem + 17408;
#pragma unroll
    for (int nb = 16; nb < 24; nb++) {
        int d0 = 8 * (nb - 16) + 2 * tql;
        float v0 = s[nb][0], v1 = s[nb][1], v2 = s[nb][2], v3 = s[nb][3];
        float h0 = bf_hi(v0), h1 = bf_hi(v1), h2 = bf_hi(v2), h3 = bf_hi(v3);
        *(__nv_bfloat16*)(VSH + d0 * 272 + ra * 2)       = __float2bfloat16(h0);
        *(__nv_bfloat16*)(VSH + (d0 + 1) * 272 + ra * 2) = __float2bfloat16(h1);
        *(__nv_bfloat16*)(VSH + d0 * 272 + rb * 2)       = __float2bfloat16(h2);
        *(__nv_bfloat16*)(VSH + (d0 + 1) * 272 + rb * 2) = __float2bfloat16(h3);
        *(__nv_bfloat16*)(VSL + d0 * 272 + ra * 2)       = __float2bfloat16(v0 - h0);
        *(__nv_bfloat16*)(VSL + (d0 + 1) * 272 + ra * 2) = __float2bfloat16(v1 - h1);
        *(__nv_bfloat16*)(VSL + d0 * 272 + rb * 2)       = __float2bfloat16(v2 - h2);
        *(__nv_bfloat16*)(VSL + (d0 + 1) * 272 + rb * 2) = __float2bfloat16(v3 - h3);
    }
    __syncthreads();
    const int bI = row0 >> 12;
    const int t0 = row0 & (T_DIM - 1);
#pragma unroll
    for (int it = 0; it < 4; it++) {
        int idx = tid + it * 256;
        int d = idx >> 4, seg = idx & 15;
        size_t gdst = ((size_t)(bI * H_DIM + d)) * T_DIM + t0 + seg * 8;
        *(uint4*)&g_VTh[gdst] = *(uint4*)(VSH + d * 272 + seg * 16);
        *(uint4*)&g_VTl[gdst] = *(uint4*)(VSL + d * 272 + seg * 16);
    }
}

// ---------------------------------------------------------------------------
// Flash attention, KTILE=64, 2 CTAs/SM. Grid 296, block 256. (round-13)
// ---------------------------------------------------------------------------
#define SQH 0
#define SQL (SQH + 128 * 144)
#define KST0 (SQL + 128 * 144)          // 36864
#define STG_SZ 36864
#define SM_TOTAL (KST0 + 2 * STG_SZ)    // 110592

__global__ __launch_bounds__(256, 2) void attn_kernel()
{
    extern __shared__ char smem[];
    const uint32_t sb = smem_u32(smem);
    const int tid  = threadIdx.x;
    const int lane = tid & 31;
    const int w    = tid >> 5;
    const int gquad = lane >> 2;
    const int tql   = lane & 3;
    const int lr    = lane & 7;
    const int lm    = lane >> 3;
    const uint32_t b_nboff = (uint32_t)(lm >> 1);
    const uint32_t b_kh    = (uint32_t)((lm & 1) << 4);
    const uint32_t a_row   = 16 * w + (lane & 15);
    const uint32_t a_colb  = (uint32_t)((lane >> 4) << 4);

    for (int item = blockIdx.x; item < NITEMS; item += GRID_W) {
        int it2 = item, gg = 7;
        while (gg > 0) {
            int cnt = 16 * (gg + 1);
            if (it2 < cnt) break;
            it2 -= cnt; gg--;
        }
        const int npg  = gg + 1;
        const int qidx = it2 / (4 * npg);
        const int r    = it2 - qidx * 4 * npg;
        const int p    = r >> 2;
        const int b    = r & 3;
        const int qt   = 4 * gg + 3 - qidx;
        const int nkv  = 2 * qt + 2;
        const int kt0  = p * nkv / npg;
        const int kt1  = (p + 1) * nkv / npg;
        const int q0   = qt * QTILE;

        const char* gqh = (const char*)(g_Qh + ((size_t)b * T_DIM + q0) * H_DIM);
        const char* gql = (const char*)(g_Ql + ((size_t)b * T_DIM + q0) * H_DIM);
        const char* gkh = (const char*)(g_Kh + (size_t)b * T_DIM * H_DIM);
        const char* gkl = (const char*)(g_Kl + (size_t)b * T_DIM * H_DIM);
        const char* gvh = (const char*)g_VTh + (size_t)b * H_DIM * T_DIM * 2;
        const char* gvl = (const char*)g_VTl + (size_t)b * H_DIM * T_DIM * 2;

#pragma unroll
        for (int it = 0; it < 4; it++) {
            int off = tid * 16 + it * 4096;
            int row = off >> 7, col = off & 127;
            cpa16(sb + SQH + row * 144 + col, gqh + off);
            cpa16(sb + SQL + row * 144 + col, gql + off);
        }
        {
            uint32_t st = sb + KST0;
#pragma unroll
            for (int it = 0; it < 2; it++) {
                int off = tid * 16 + it * 4096;
                int row = off >> 7, col = off & 127;
                cpa16(st + row * 144 + col, gkh + (size_t)kt0 * 8192 + off);
                cpa16(st + 9216 + row * 144 + col, gkl + (size_t)kt0 * 8192 + off);
                cpa16(st + 18432 + row * 144 + col,
                      gvh + (size_t)row * (T_DIM * 2) + kt0 * 128 + col);
                cpa16(st + 27648 + row * 144 + col,
                      gvl + (size_t)row * (T_DIM * 2) + kt0 * 128 + col);
            }
        }
        CP_COMMIT;

        float o[8][4];
#pragma unroll
        for (int d = 0; d < 8; d++)
#pragma unroll
            for (int e = 0; e < 4; e++) o[d][e] = 0.f;
        float m_a = -1e30f, m_b = -1e30f, l_a = 0.f, l_b = 0.f;

        const int row_a = q0 + 16 * w + gquad;
        const int row_b = row_a + 8;

        for (int kt = kt0; kt < kt1; kt++) {
            const int kv0 = kt * KT64;
            if (kt + 1 < kt1) {
                uint32_t st = sb + KST0 + ((kt + 1 - kt0) & 1) * STG_SZ;
                const size_t ko = (size_t)(kt + 1) * 8192;
                const int vo = (kt + 1) * 128;
#pragma unroll
                for (int it = 0; it < 2; it++) {
                    int off = tid * 16 + it * 4096;
                    int row = off >> 7, col = off & 127;
                    cpa16(st + row * 144 + col, gkh + ko + off);
                    cpa16(st + 9216 + row * 144 + col, gkl + ko + off);
                    cpa16(st + 18432 + row * 144 + col,
                          gvh + (size_t)row * (T_DIM * 2) + vo + col);
                    cpa16(st + 27648 + row * 144 + col,
                          gvl + (size_t)row * (T_DIM * 2) + vo + col);
                }
                CP_COMMIT;
                CP_WAIT1;
            } else {
                CP_WAIT0;
            }
            __syncthreads();

            const uint32_t stg = sb + KST0 + ((kt - kt0) & 1) * STG_SZ;

            float s[8][4];
#pragma unroll
            for (int nb = 0; nb < 8; nb++)
#pragma unroll
                for (int e = 0; e < 4; e++) s[nb][e] = 0.f;

#pragma unroll
            for (int ks = 0; ks < 4; ks++) {
                uint32_t ah[4], al[4];
                ldsm_x4(ah[0], ah[1], ah[2], ah[3], sb + SQH + a_row * 144 + ks * 32 + a_colb);
                ldsm_x4(al[0], al[1], al[2], al[3], sb + SQL + a_row * 144 + ks * 32 + a_colb);
#pragma unroll
                for (int nbp = 0; nbp < 4; nbp++) {
                    int nb = 2 * nbp;
                    uint32_t baddr = (8 * (nb + b_nboff) + lr) * 144 + ks * 32 + b_kh;
                    uint32_t h0, h1, h2, h3, l0, l1, l2, l3;
                    ldsm_x4(h0, h1, h2, h3, stg + baddr);
                    ldsm_x4(l0, l1, l2, l3, stg + 9216 + baddr);
                    mma16816(s[nb], ah, h0, h1);
                    mma16816(s[nb], ah, l0, l1);
                    mma16816(s[nb], al, h0, h1);
                    mma16816(s[nb + 1], ah, h2, h3);
                    mma16816(s[nb + 1], ah, l2, l3);
                    mma16816(s[nb + 1], al, h2, h3);
                }
            }

            if (kt >= 2 * qt) {
#pragma unroll
                for (int nb = 0; nb < 8; nb++) {
                    int colg = kv0 + 8 * nb + 2 * tql;
                    if (colg > row_a)     s[nb][0] = -1e30f;
                    if (colg + 1 > row_a) s[nb][1] = -1e30f;
                    if (colg > row_b)     s[nb][2] = -1e30f;
                    if (colg + 1 > row_b) s[nb][3] = -1e30f;
                }
            }

            float mt_a = -1e30f, mt_b = -1e30f;
#pragma unroll
            for (int nb = 0; nb < 8; nb++) {
                mt_a = fmaxf(mt_a, fmaxf(s[nb][0], s[nb][1]));
                mt_b = fmaxf(mt_b, fmaxf(s[nb][2], s[nb][3]));
            }
            mt_a = fmaxf(mt_a, __shfl_xor_sync(0xffffffffu, mt_a, 1));
            mt_a = fmaxf(mt_a, __shfl_xor_sync(0xffffffffu, mt_a, 2));
            mt_b = fmaxf(mt_b, __shfl_xor_sync(0xffffffffu, mt_b, 1));
            mt_b = fmaxf(mt_b, __shfl_xor_sync(0xffffffffu, mt_b, 2));

            float mn_a = fmaxf(m_a, mt_a), mn_b = fmaxf(m_b, mt_b);
            float al_a = ex2f(m_a - mn_a), al_b = ex2f(m_b - mn_b);
            m_a = mn_a; m_b = mn_b;

            float sum_a = 0.f, sum_b = 0.f;
#pragma unroll
            for (int nb = 0; nb < 8; nb++) {
                s[nb][0] = ex2f(s[nb][0] - mn_a);
                s[nb][1] = ex2f(s[nb][1] - mn_a);
                s[nb][2] = ex2f(s[nb][2] - mn_b);
                s[nb][3] = ex2f(s[nb][3] - mn_b);
                sum_a += s[nb][0] + s[nb][1];
                sum_b += s[nb][2] + s[nb][3];
            }
            sum_a += __shfl_xor_sync(0xffffffffu, sum_a, 1);
            sum_a += __shfl_xor_sync(0xffffffffu, sum_a, 2);
            sum_b += __shfl_xor_sync(0xffffffffu, sum_b, 1);
            sum_b += __shfl_xor_sync(0xffffffffu, sum_b, 2);
            l_a = l_a * al_a + sum_a;
            l_b = l_b * al_b + sum_b;

#pragma unroll
            for (int d = 0; d < 8; d++) {
                o[d][0] *= al_a; o[d][1] *= al_a;
                o[d][2] *= al_b; o[d][3] *= al_b;
            }

#pragma unroll
            for (int j = 0; j < 4; j++) {
                uint32_t ph[4], pl[4];
                float p00 = s[2 * j][0],     p01 = s[2 * j][1];
                float p02 = s[2 * j][2],     p03 = s[2 * j][3];
                float p10 = s[2 * j + 1][0], p11 = s[2 * j + 1][1];
                float p12 = s[2 * j + 1][2], p13 = s[2 * j + 1][3];
                float h00 = bf_hi(p00), h01 = bf_hi(p01), h02 = bf_hi(p02), h03 = bf_hi(p03);
                float h10 = bf_hi(p10), h11 = bf_hi(p11), h12 = bf_hi(p12), h13 = bf_hi(p13);
                ph[0] = pack_bf16(h00, h01); ph[1] = pack_bf16(h02, h03);
                ph[2] = pack_bf16(h10, h11); ph[3] = pack_bf16(h12, h13);
                pl[0] = pack_bf16(p00 - h00, p01 - h01);
                pl[1] = pack_bf16(p02 - h02, p03 - h03);
                pl[2] = pack_bf16(p10 - h10, p11 - h11);
                pl[3] = pack_bf16(p12 - h12, p13 - h13);
#pragma unroll
                for (int dp = 0; dp < 4; dp++) {
                    int d = 2 * dp;
                    uint32_t vaddr = (8 * (d + b_nboff) + lr) * 144 + j * 32 + b_kh;
                    uint32_t h0, h1, h2, h3, l0, l1, l2, l3;
                    ldsm_x4(h0, h1, h2, h3, stg + 18432 + vaddr);
                    ldsm_x4(l0, l1, l2, l3, stg + 27648 + vaddr);
                    mma16816(o[d], ph, h0, h1);
                    mma16816(o[d], ph, l0, l1);
                    mma16816(o[d], pl, h0, h1);
                    mma16816(o[d + 1], ph, h2, h3);
                    mma16816(o[d + 1], ph, l2, l3);
                    mma16816(o[d + 1], pl, h2, h3);
                }
            }
            __syncthreads();
        }

        {
            float* Op = g_Op + (size_t)(p * B_DIM + b) * T_DIM * H_DIM;
            float2* MLp = g_ML + (size_t)(p * B_DIM + b) * T_DIM;
#pragma unroll
            for (int d = 0; d < 8; d++) {
                int col = 8 * d + 2 * tql;
                *(float2*)&Op[(size_t)row_a * H_DIM + col] = make_float2(o[d][0], o[d][1]);
                *(float2*)&Op[(size_t)row_b * H_DIM + col] = make_float2(o[d][2], o[d][3]);
            }
            if (tql == 0) {
                MLp[row_a] = make_float2(m_a, l_a);
                MLp[row_b] = make_float2(m_b, l_b);
            }
        }
    }
}

// ---------------------------------------------------------------------------
// Combine partials -> out. Vectorized float4/thread. Grid 1024 x 256.
// ---------------------------------------------------------------------------
__global__ __launch_bounds__(256) void combine_kernel(float* __restrict__ out)
{
    int idx = blockIdx.x * 256 + threadIdx.x;   // < 4*4096*16
    int c   = (idx & 15) * 4;
    int pr  = idx >> 4;
    int b   = pr >> 12;
    int t   = pr & (T_DIM - 1);
    int np  = (t >> 9) + 1;

    float2 mls[8];
    float mmax = -1e30f;
#pragma unroll 8
    for (int p = 0; p < 8; p++) {
        if (p < np) {
            mls[p] = g_ML[(size_t)(p * B_DIM + b) * T_DIM + t];
            mmax = fmaxf(mmax, mls[p].x);
        }
    }
    float l = 0.f;
    float4 ov = make_float4(0.f, 0.f, 0.f, 0.f);
#pragma unroll 8
    for (int p = 0; p < 8; p++) {
        if (p < np) {
            float wgt = ex2f(mls[p].x - mmax);
            l += mls[p].y * wgt;
            float4 v = *(const float4*)&g_Op[((size_t)(p * B_DIM + b) * T_DIM + t) * H_DIM + c];
            ov.x += v.x * wgt; ov.y += v.y * wgt;
            ov.z += v.z * wgt; ov.w += v.w * wgt;
        }
    }
    float inv = 1.f / l;
    *(float4*)&out[((size_t)b * T_DIM + t) * H_DIM + c] =
        make_float4(ov.x * inv, ov.y * inv, ov.z * inv, ov.w * inv);
}

// ---------------------------------------------------------------------------
extern "C" void kernel_launch(void* const* d_in, const int* in_sizes, int n_in,
                              void* d_out, int out_size)
{
    (void)in_sizes; (void)n_in; (void)out_size;
    const float* x  = (const float*)d_in[0];
    const float* Wq = (const float*)d_in[1];
    const float* Wk = (const float*)d_in[2];
    const float* Wv = (const float*)d_in[3];
    float* out = (float*)d_out;

    splitw_kernel<<<192, 256>>>(Wq, Wk, Wv);

    cudaFuncSetAttribute(proj_kernel,
                         cudaFuncAttributeMaxDynamicSharedMemorySize, PSM_TOTAL);
    proj_kernel<<<128, 256, PSM_TOTAL>>>(x);

    cudaFuncSetAttribute(attn_kernel,
                         cudaFuncAttributeMaxDynamicSharedMemorySize, SM_TOTAL);
    attn_kernel<<<GRID_W, 256, SM_TOTAL>>>();

    combine_kernel<<<1024, 256>>>(out);
}

// round 17
// speedup vs baseline: 1.5265x; 1.5265x over previous
#include <cuda_runtime.h>
#include <cuda_bf16.h>
#include <stdint.h>

#define B_DIM 4
#define T_DIM 4096
#define C_DIM 1024
#define H_DIM 64
#define QTILE 128
#define KT64  64
#define GRID_W 296
#define NITEMS 576

// ---- device scratch (no cudaMalloc allowed) ----
__device__ __align__(16) __nv_bfloat16 g_wh[3 * C_DIM * H_DIM];
__device__ __align__(16) __nv_bfloat16 g_wl[3 * C_DIM * H_DIM];
__device__ __align__(16) __nv_bfloat16 g_Qh[B_DIM * T_DIM * H_DIM];
__device__ __align__(16) __nv_bfloat16 g_Ql[B_DIM * T_DIM * H_DIM];
__device__ __align__(16) __nv_bfloat16 g_Kh[B_DIM * T_DIM * H_DIM];
__device__ __align__(16) __nv_bfloat16 g_Kl[B_DIM * T_DIM * H_DIM];
__device__ __align__(16) __nv_bfloat16 g_VTh[B_DIM * H_DIM * T_DIM];  // [b][d][t]
__device__ __align__(16) __nv_bfloat16 g_VTl[B_DIM * H_DIM * T_DIM];
__device__ __align__(16) float  g_Op[8 * B_DIM * T_DIM * H_DIM];      // [p][b][t][d]
__device__ __align__(16) float2 g_ML[8 * B_DIM * T_DIM];              // [p][b][t]

#define Q_SCALE 0.04508422002778f   // 1/sqrt(1024) * log2(e)

__device__ __forceinline__ uint32_t smem_u32(const void* p) {
    uint32_t a;
    asm("{ .reg .u64 t; cvta.to.shared.u64 t, %1; cvt.u32.u64 %0, t; }"
        : "=r"(a) : "l"(p));
    return a;
}
__device__ __forceinline__ float ex2f(float x) {
    float y; asm("ex2.approx.ftz.f32 %0, %1;" : "=f"(y) : "f"(x)); return y;
}
__device__ __forceinline__ uint32_t pack_bf16(float a, float b) {
    __nv_bfloat162 t = __floats2bfloat162_rn(a, b);
    return *reinterpret_cast<uint32_t*>(&t);
}
__device__ __forceinline__ float bf_hi(float v) {
    return __bfloat162float(__float2bfloat16(v));
}
__device__ __forceinline__ void ldsm_x4(uint32_t& r0, uint32_t& r1,
                                        uint32_t& r2, uint32_t& r3, uint32_t a) {
    asm volatile("ldmatrix.sync.aligned.m8n8.x4.shared.b16 {%0,%1,%2,%3}, [%4];"
                 : "=r"(r0), "=r"(r1), "=r"(r2), "=r"(r3) : "r"(a));
}
__device__ __forceinline__ void ldsm_x4_t(uint32_t& r0, uint32_t& r1,
                                          uint32_t& r2, uint32_t& r3, uint32_t a) {
    asm volatile("ldmatrix.sync.aligned.m8n8.x4.trans.shared.b16 {%0,%1,%2,%3}, [%4];"
                 : "=r"(r0), "=r"(r1), "=r"(r2), "=r"(r3) : "r"(a));
}
__device__ __forceinline__ void mma16816(float* c, const uint32_t* a,
                                         uint32_t b0, uint32_t b1) {
    asm volatile("mma.sync.aligned.m16n8k16.row.col.f32.bf16.bf16.f32 "
                 "{%0,%1,%2,%3}, {%4,%5,%6,%7}, {%8,%9}, {%0,%1,%2,%3};"
                 : "+f"(c[0]), "+f"(c[1]), "+f"(c[2]), "+f"(c[3])
                 : "r"(a[0]), "r"(a[1]), "r"(a[2]), "r"(a[3]), "r"(b0), "r"(b1));
}
__device__ __forceinline__ void cpa16(uint32_t s, const void* g) {
    asm volatile("cp.async.cg.shared.global [%0], [%1], 16;" :: "r"(s), "l"(g) : "memory");
}
#define CP_COMMIT asm volatile("cp.async.commit_group;" ::: "memory")
#define CP_WAIT1  asm volatile("cp.async.wait_group 1;" ::: "memory")
#define CP_WAIT0  asm volatile("cp.async.wait_group 0;" ::: "memory")

// ---------------------------------------------------------------------------
// Split W (3 x 1024 x 64) into bf16 hi/lo. grid 192 x 256.
// ---------------------------------------------------------------------------
__global__ __launch_bounds__(256) void splitw_kernel(
    const float* __restrict__ Wq, const float* __restrict__ Wk,
    const float* __restrict__ Wv)
{
    int idx = blockIdx.x * 256 + threadIdx.x;
    int m = idx >> 14;
    int rem = idx & 16383;
    const float* W = (m == 0) ? Wq : (m == 1) ? Wk : Wv;
    float4 v = ((const float4*)W)[rem];
    float h0 = bf_hi(v.x), h1 = bf_hi(v.y), h2 = bf_hi(v.z), h3 = bf_hi(v.w);
    ((uint2*)g_wh)[idx] = make_uint2(pack_bf16(h0, h1), pack_bf16(h2, h3));
    ((uint2*)g_wl)[idx] = make_uint2(pack_bf16(v.x - h0, v.y - h1),
                                     pack_bf16(v.z - h2, v.w - h3));
}

// ---------------------------------------------------------------------------
// QKV projection (fused): fp32 x staged via cp.async, split to bf16 in-kernel
// ONCE, all 3 matrices per CTA. Grid 128, block 256.
// ---------------------------------------------------------------------------
#define PXF 0
#define PXF_SZ (128 * 272)            // 34816 per stage (fp32 x, 272B stride)
#define PXH (2 * PXF_SZ)              // 69632 (bf16 hi, 144B stride)
#define PXL (PXH + 18432)             // 88064
#define PW  (PXL + 18432)             // 106496
#define PW_SZ 51200                   // per stage: WH 25600 + WL 25600
#define PSM_TOTAL (PW + 2 * PW_SZ)    // 208896

__global__ __launch_bounds__(256) void proj_kernel(const float* __restrict__ x)
{
    extern __shared__ char smem[];
    const uint32_t sb = smem_u32(smem);
    const int tid  = threadIdx.x;
    const int lane = tid & 31;
    const int w    = tid >> 5;
    const int gquad = lane >> 2;
    const int tql   = lane & 3;
    const int lr    = lane & 7;
    const uint32_t kofs = (uint32_t)(((lane >> 3) & 1) << 3);
    const uint32_t nofs = (uint32_t)((lane >> 4) << 3);

    const int row0 = blockIdx.x * 128;
    const float* xsrc = x + (size_t)row0 * C_DIM;

    auto load_stage = [&](int kc, int st) {
        uint32_t xf = sb + PXF + st * PXF_SZ;
#pragma unroll
        for (int it = 0; it < 8; it++) {
            int idx = tid + it * 256;          // 2048 float4
            int row = idx >> 4, seg = idx & 15;
            cpa16(xf + row * 272 + seg * 16, xsrc + (size_t)row * C_DIM + kc * 64 + seg * 4);
        }
        uint32_t wb = sb + PW + st * PW_SZ;
#pragma unroll
        for (int it = 0; it < 6; it++) {
            int idx = tid + it * 256;          // 1536
            int kr = idx / 24, s24 = idx - kr * 24;
            int m = s24 >> 3, seg = s24 & 7;
            size_t gsrc = ((size_t)m * C_DIM + kc * 64 + kr) * H_DIM + seg * 8;
            cpa16(wb + kr * 400 + s24 * 16, g_wh + gsrc);
            cpa16(wb + 25600 + kr * 400 + s24 * 16, g_wl + gsrc);
        }
    };

    load_stage(0, 0);
    CP_COMMIT;

    float s[24][4];
#pragma unroll
    for (int nb = 0; nb < 24; nb++)
#pragma unroll
        for (int e = 0; e < 4; e++) s[nb][e] = 0.f;

    const uint32_t a_row = 16 * w + (lane & 15);
    const uint32_t a_colb = (uint32_t)((lane >> 4) << 4);

    for (int kc = 0; kc < 16; kc++) {
        if (kc < 15) { load_stage(kc + 1, (kc + 1) & 1); CP_COMMIT; CP_WAIT1; }
        else         { CP_WAIT0; }
        __syncthreads();   // stage kc ready

        // convert fp32 x chunk -> split bf16 (single-buffered Xbf)
        {
            const char* xf = smem + PXF + (kc & 1) * PXF_SZ;
#pragma unroll
            for (int it = 0; it < 8; it++) {
                int idx = tid + it * 256;
                int row = idx >> 4, seg = idx & 15;
                float4 v = *(const float4*)(xf + row * 272 + seg * 16);
                float h0 = bf_hi(v.x), h1 = bf_hi(v.y), h2 = bf_hi(v.z), h3 = bf_hi(v.w);
                *(uint32_t*)(smem + PXH + row * 144 + seg * 8)     = pack_bf16(h0, h1);
                *(uint32_t*)(smem + PXH + row * 144 + seg * 8 + 4) = pack_bf16(h2, h3);
                *(uint32_t*)(smem + PXL + row * 144 + seg * 8)     = pack_bf16(v.x - h0, v.y - h1);
                *(uint32_t*)(smem + PXL + row * 144 + seg * 8 + 4) = pack_bf16(v.z - h2, v.w - h3);
            }
        }
        __syncthreads();   // Xbf visible

        const uint32_t wbase = sb + PW + (kc & 1) * PW_SZ;
#pragma unroll
        for (int ks = 0; ks < 4; ks++) {
            uint32_t ah[4], al[4];
            ldsm_x4(ah[0], ah[1], ah[2], ah[3], sb + PXH + a_row * 144 + ks * 32 + a_colb);
            ldsm_x4(al[0], al[1], al[2], al[3], sb + PXL + a_row * 144 + ks * 32 + a_colb);
            const uint32_t wrow = (uint32_t)(ks * 16) + kofs + lr;
#pragma unroll
            for (int np = 0; np < 12; np++) {
                uint32_t woff = wrow * 400 + (np * 16 + nofs) * 2;
                uint32_t h0, h1, h2, h3, l0, l1, l2, l3;
                ldsm_x4_t(h0, h1, h2, h3, wbase + woff);
                ldsm_x4_t(l0, l1, l2, l3, wbase + 25600 + woff);
                mma16816(s[2 * np], ah, h0, h1);
                mma16816(s[2 * np], ah, l0, l1);
                mma16816(s[2 * np], al, h0, h1);
                mma16816(s[2 * np + 1], ah, h2, h3);
                mma16816(s[2 * np + 1], ah, l2, l3);
                mma16816(s[2 * np + 1], al, h2, h3);
            }
        }
        // RACE FIX: next iteration's load_stage overwrites same-parity buffers
        // that lagging warps may still be reading. Barrier before next cp.async.
        __syncthreads();
    }

    // ---- epilogue ----
    const int ra = 16 * w + gquad;
    const int rb = ra + 8;
    const size_t ga = (size_t)(row0 + ra) * H_DIM;
    const size_t gb = (size_t)(row0 + rb) * H_DIM;

#pragma unroll
    for (int nb = 0; nb < 8; nb++) {   // Q (scaled)
        int col = 8 * nb + 2 * tql;
        float q0 = s[nb][0] * Q_SCALE, q1 = s[nb][1] * Q_SCALE;
        float q2 = s[nb][2] * Q_SCALE, q3 = s[nb][3] * Q_SCALE;
        float h0 = bf_hi(q0), h1 = bf_hi(q1), h2 = bf_hi(q2), h3 = bf_hi(q3);
        *(uint32_t*)&g_Qh[ga + col] = pack_bf16(h0, h1);
        *(uint32_t*)&g_Ql[ga + col] = pack_bf16(q0 - h0, q1 - h1);
        *(uint32_t*)&g_Qh[gb + col] = pack_bf16(h2, h3);
        *(uint32_t*)&g_Ql[gb + col] = pack_bf16(q2 - h2, q3 - h3);
    }
#pragma unroll
    for (int nb = 8; nb < 16; nb++) {  // K
        int col = 8 * (nb - 8) + 2 * tql;
        float k0 = s[nb][0], k1 = s[nb][1], k2 = s[nb][2], k3 = s[nb][3];
        float h0 = bf_hi(k0), h1 = bf_hi(k1), h2 = bf_hi(k2), h3 = bf_hi(k3);
        *(uint32_t*)&g_Kh[ga + col] = pack_bf16(h0, h1);
        *(uint32_t*)&g_Kl[ga + col] = pack_bf16(k0 - h0, k1 - h1);
        *(uint32_t*)&g_Kh[gb + col] = pack_bf16(h2, h3);
        *(uint32_t*)&g_Kl[gb + col] = pack_bf16(k2 - h2, k3 - h3);
    }
    // V transposed staging in the (now free) XF region.
    char* VSH = smem;              // 64 x 272B
    char* VSL = smem + 17408;
#pragma unroll
    for (int nb = 16; nb < 24; nb++) {
        int d0 = 8 * (nb - 16) + 2 * tql;
        float v0 = s[nb][0], v1 = s[nb][1], v2 = s[nb][2], v3 = s[nb][3];
        float h0 = bf_hi(v0), h1 = bf_hi(v1), h2 = bf_hi(v2), h3 = bf_hi(v3);
        *(__nv_bfloat16*)(VSH + d0 * 272 + ra * 2)       = __float2bfloat16(h0);
        *(__nv_bfloat16*)(VSH + (d0 + 1) * 272 + ra * 2) = __float2bfloat16(h1);
        *(__nv_bfloat16*)(VSH + d0 * 272 + rb * 2)       = __float2bfloat16(h2);
        *(__nv_bfloat16*)(VSH + (d0 + 1) * 272 + rb * 2) = __float2bfloat16(h3);
        *(__nv_bfloat16*)(VSL + d0 * 272 + ra * 2)       = __float2bfloat16(v0 - h0);
        *(__nv_bfloat16*)(VSL + (d0 + 1) * 272 + ra * 2) = __float2bfloat16(v1 - h1);
        *(__nv_bfloat16*)(VSL + d0 * 272 + rb * 2)       = __float2bfloat16(v2 - h2);
        *(__nv_bfloat16*)(VSL + (d0 + 1) * 272 + rb * 2) = __float2bfloat16(v3 - h3);
    }
    __syncthreads();
    const int bI = row0 >> 12;
    const int t0 = row0 & (T_DIM - 1);
#pragma unroll
    for (int it = 0; it < 4; it++) {
        int idx = tid + it * 256;
        int d = idx >> 4, seg = idx & 15;
        size_t gdst = ((size_t)(bI * H_DIM + d)) * T_DIM + t0 + seg * 8;
        *(uint4*)&g_VTh[gdst] = *(uint4*)(VSH + d * 272 + seg * 16);
        *(uint4*)&g_VTl[gdst] = *(uint4*)(VSL + d * 272 + seg * 16);
    }
}

// ---------------------------------------------------------------------------
// Flash attention, KTILE=64, 2 CTAs/SM. Grid 296, block 256.
// Single-barrier mainloop: [wait0 -> sync -> prefetch(next) -> compute].
// ---------------------------------------------------------------------------
#define SQH 0
#define SQL (SQH + 128 * 144)
#define KST0 (SQL + 128 * 144)          // 36864
#define STG_SZ 36864
#define SM_TOTAL (KST0 + 2 * STG_SZ)    // 110592

__global__ __launch_bounds__(256, 2) void attn_kernel()
{
    extern __shared__ char smem[];
    const uint32_t sb = smem_u32(smem);
    const int tid  = threadIdx.x;
    const int lane = tid & 31;
    const int w    = tid >> 5;
    const int gquad = lane >> 2;
    const int tql   = lane & 3;
    const int lr    = lane & 7;
    const int lm    = lane >> 3;
    const uint32_t b_nboff = (uint32_t)(lm >> 1);
    const uint32_t b_kh    = (uint32_t)((lm & 1) << 4);
    const uint32_t a_row   = 16 * w + (lane & 15);
    const uint32_t a_colb  = (uint32_t)((lane >> 4) << 4);

    for (int item = blockIdx.x; item < NITEMS; item += GRID_W) {
        int it2 = item, gg = 7;
        while (gg > 0) {
            int cnt = 16 * (gg + 1);
            if (it2 < cnt) break;
            it2 -= cnt; gg--;
        }
        const int npg  = gg + 1;
        const int qidx = it2 / (4 * npg);
        const int r    = it2 - qidx * 4 * npg;
        const int p    = r >> 2;
        const int b    = r & 3;
        const int qt   = 4 * gg + 3 - qidx;
        const int nkv  = 2 * qt + 2;
        const int kt0  = p * nkv / npg;
        const int kt1  = (p + 1) * nkv / npg;
        const int q0   = qt * QTILE;

        const char* gqh = (const char*)(g_Qh + ((size_t)b * T_DIM + q0) * H_DIM);
        const char* gql = (const char*)(g_Ql + ((size_t)b * T_DIM + q0) * H_DIM);
        const char* gkh = (const char*)(g_Kh + (size_t)b * T_DIM * H_DIM);
        const char* gkl = (const char*)(g_Kl + (size_t)b * T_DIM * H_DIM);
        const char* gvh = (const char*)g_VTh + (size_t)b * H_DIM * T_DIM * 2;
        const char* gvl = (const char*)g_VTl + (size_t)b * H_DIM * T_DIM * 2;

        // Cross-item hazard: lagging warps of the previous item may still be
        // reading Q/stage smem that the prologue below overwrites.
        __syncthreads();

        // ---- prologue: Q + first stage (one cp.async group) ----
#pragma unroll
        for (int it = 0; it < 4; it++) {
            int off = tid * 16 + it * 4096;
            int row = off >> 7, col = off & 127;
            cpa16(sb + SQH + row * 144 + col, gqh + off);
            cpa16(sb + SQL + row * 144 + col, gql + off);
        }
        {
            uint32_t st = sb + KST0;
#pragma unroll
            for (int it = 0; it < 2; it++) {
                int off = tid * 16 + it * 4096;
                int row = off >> 7, col = off & 127;
                cpa16(st + row * 144 + col, gkh + (size_t)kt0 * 8192 + off);
                cpa16(st + 9216 + row * 144 + col, gkl + (size_t)kt0 * 8192 + off);
                cpa16(st + 18432 + row * 144 + col,
                      gvh + (size_t)row * (T_DIM * 2) + kt0 * 128 + col);
                cpa16(st + 27648 + row * 144 + col,
                      gvl + (size_t)row * (T_DIM * 2) + kt0 * 128 + col);
            }
        }
        CP_COMMIT;

        float o[8][4];
#pragma unroll
        for (int d = 0; d < 8; d++)
#pragma unroll
            for (int e = 0; e < 4; e++) o[d][e] = 0.f;
        float m_a = -1e30f, m_b = -1e30f, l_a = 0.f, l_b = 0.f;

        const int row_a = q0 + 16 * w + gquad;
        const int row_b = row_a + 8;

        for (int kt = kt0; kt < kt1; kt++) {
            const int kv0 = kt * KT64;

            // Stage kt was committed one full compute-phase ago (or prologue).
            CP_WAIT0;
            __syncthreads();   // all threads' slices visible; prev compute done

            // Prefetch next stage into the other buffer (safe: that buffer's
            // last readers finished before the sync above).
            if (kt + 1 < kt1) {
                uint32_t st = sb + KST0 + ((kt + 1 - kt0) & 1) * STG_SZ;
                const size_t ko = (size_t)(kt + 1) * 8192;
                const int vo = (kt + 1) * 128;
#pragma unroll
                for (int it = 0; it < 2; it++) {
                    int off = tid * 16 + it * 4096;
                    int row = off >> 7, col = off & 127;
                    cpa16(st + row * 144 + col, gkh + ko + off);
                    cpa16(st + 9216 + row * 144 + col, gkl + ko + off);
                    cpa16(st + 18432 + row * 144 + col,
                          gvh + (size_t)row * (T_DIM * 2) + vo + col);
                    cpa16(st + 27648 + row * 144 + col,
                          gvl + (size_t)row * (T_DIM * 2) + vo + col);
                }
                CP_COMMIT;
            }

            const uint32_t stg = sb + KST0 + ((kt - kt0) & 1) * STG_SZ;

            float s[8][4];
#pragma unroll
            for (int nb = 0; nb < 8; nb++)
#pragma unroll
                for (int e = 0; e < 4; e++) s[nb][e] = 0.f;

#pragma unroll
            for (int ks = 0; ks < 4; ks++) {
                uint32_t ah[4], al[4];
                ldsm_x4(ah[0], ah[1], ah[2], ah[3], sb + SQH + a_row * 144 + ks * 32 + a_colb);
                ldsm_x4(al[0], al[1], al[2], al[3], sb + SQL + a_row * 144 + ks * 32 + a_colb);
#pragma unroll
                for (int nbp = 0; nbp < 4; nbp++) {
                    int nb = 2 * nbp;
                    uint32_t baddr = (8 * (nb + b_nboff) + lr) * 144 + ks * 32 + b_kh;
                    uint32_t h0, h1, h2, h3, l0, l1, l2, l3;
                    ldsm_x4(h0, h1, h2, h3, stg + baddr);
                    ldsm_x4(l0, l1, l2, l3, stg + 9216 + baddr);
                    mma16816(s[nb], ah, h0, h1);
                    mma16816(s[nb], ah, l0, l1);
                    mma16816(s[nb], al, h0, h1);
                    mma16816(s[nb + 1], ah, h2, h3);
                    mma16816(s[nb + 1], ah, l2, l3);
                    mma16816(s[nb + 1], al, h2, h3);
                }
            }

            if (kt >= 2 * qt) {
#pragma unroll
                for (int nb = 0; nb < 8; nb++) {
                    int colg = kv0 + 8 * nb + 2 * tql;
                    if (colg > row_a)     s[nb][0] = -1e30f;
                    if (colg + 1 > row_a) s[nb][1] = -1e30f;
                    if (colg > row_b)     s[nb][2] = -1e30f;
                    if (colg + 1 > row_b) s[nb][3] = -1e30f;
                }
            }

            float mt_a = -1e30f, mt_b = -1e30f;
#pragma unroll
            for (int nb = 0; nb < 8; nb++) {
                mt_a = fmaxf(mt_a, fmaxf(s[nb][0], s[nb][1]));
                mt_b = fmaxf(mt_b, fmaxf(s[nb][2], s[nb][3]));
            }
            mt_a = fmaxf(mt_a, __shfl_xor_sync(0xffffffffu, mt_a, 1));
            mt_a = fmaxf(mt_a, __shfl_xor_sync(0xffffffffu, mt_a, 2));
            mt_b = fmaxf(mt_b, __shfl_xor_sync(0xffffffffu, mt_b, 1));
            mt_b = fmaxf(mt_b, __shfl_xor_sync(0xffffffffu, mt_b, 2));

            float mn_a = fmaxf(m_a, mt_a), mn_b = fmaxf(m_b, mt_b);
            float al_a = ex2f(m_a - mn_a), al_b = ex2f(m_b - mn_b);
            m_a = mn_a; m_b = mn_b;

            float sum_a = 0.f, sum_b = 0.f;
#pragma unroll
            for (int nb = 0; nb < 8; nb++) {
                s[nb][0] = ex2f(s[nb][0] - mn_a);
                s[nb][1] = ex2f(s[nb][1] - mn_a);
                s[nb][2] = ex2f(s[nb][2] - mn_b);
                s[nb][3] = ex2f(s[nb][3] - mn_b);
                sum_a += s[nb][0] + s[nb][1];
                sum_b += s[nb][2] + s[nb][3];
            }
            sum_a += __shfl_xor_sync(0xffffffffu, sum_a, 1);
            sum_a += __shfl_xor_sync(0xffffffffu, sum_a, 2);
            sum_b += __shfl_xor_sync(0xffffffffu, sum_b, 1);
            sum_b += __shfl_xor_sync(0xffffffffu, sum_b, 2);
            l_a = l_a * al_a + sum_a;
            l_b = l_b * al_b + sum_b;

#pragma unroll
            for (int d = 0; d < 8; d++) {
                o[d][0] *= al_a; o[d][1] *= al_a;
                o[d][2] *= al_b; o[d][3] *= al_b;
            }

#pragma unroll
            for (int j = 0; j < 4; j++) {
                uint32_t ph[4], pl[4];
                float p00 = s[2 * j][0],     p01 = s[2 * j][1];
                float p02 = s[2 * j][2],     p03 = s[2 * j][3];
                float p10 = s[2 * j + 1][0], p11 = s[2 * j + 1][1];
                float p12 = s[2 * j + 1][2], p13 = s[2 * j + 1][3];
                float h00 = bf_hi(p00), h01 = bf_hi(p01), h02 = bf_hi(p02), h03 = bf_hi(p03);
                float h10 = bf_hi(p10), h11 = bf_hi(p11), h12 = bf_hi(p12), h13 = bf_hi(p13);
                ph[0] = pack_bf16(h00, h01); ph[1] = pack_bf16(h02, h03);
                ph[2] = pack_bf16(h10, h11); ph[3] = pack_bf16(h12, h13);
                pl[0] = pack_bf16(p00 - h00, p01 - h01);
                pl[1] = pack_bf16(p02 - h02, p03 - h03);
                pl[2] = pack_bf16(p10 - h10, p11 - h11);
                pl[3] = pack_bf16(p12 - h12, p13 - h13);
#pragma unroll
                for (int dp = 0; dp < 4; dp++) {
                    int d = 2 * dp;
                    uint32_t vaddr = (8 * (d + b_nboff) + lr) * 144 + j * 32 + b_kh;
                    uint32_t h0, h1, h2, h3, l0, l1, l2, l3;
                    ldsm_x4(h0, h1, h2, h3, stg + 18432 + vaddr);
                    ldsm_x4(l0, l1, l2, l3, stg + 27648 + vaddr);
                    mma16816(o[d], ph, h0, h1);
                    mma16816(o[d], ph, l0, l1);
                    mma16816(o[d], pl, h0, h1);
                    mma16816(o[d + 1], ph, h2, h3);
                    mma16816(o[d + 1], ph, l2, l3);
                    mma16816(o[d + 1], pl, h2, h3);
                }
            }
            // no trailing barrier: next iteration's wait0+sync provides it
        }

        {
            float* Op = g_Op + (size_t)(p * B_DIM + b) * T_DIM * H_DIM;
            float2* MLp = g_ML + (size_t)(p * B_DIM + b) * T_DIM;
#pragma unroll
            for (int d = 0; d < 8; d++) {
                int col = 8 * d + 2 * tql;
                *(float2*)&Op[(size_t)row_a * H_DIM + col] = make_float2(o[d][0], o[d][1]);
                *(float2*)&Op[(size_t)row_b * H_DIM + col] = make_float2(o[d][2], o[d][3]);
            }
            if (tql == 0) {
                MLp[row_a] = make_float2(m_a, l_a);
                MLp[row_b] = make_float2(m_b, l_b);
            }
        }
    }
}

// ---------------------------------------------------------------------------
// Combine partials -> out. Vectorized float4/thread. Grid 1024 x 256.
// ---------------------------------------------------------------------------
__global__ __launch_bounds__(256) void combine_kernel(float* __restrict__ out)
{
    int idx = blockIdx.x * 256 + threadIdx.x;   // < 4*4096*16
    int c   = (idx & 15) * 4;
    int pr  = idx >> 4;
    int b   = pr >> 12;
    int t   = pr & (T_DIM - 1);
    int np  = (t >> 9) + 1;

    float2 mls[8];
    float mmax = -1e30f;
#pragma unroll 8
    for (int p = 0; p < 8; p++) {
        if (p < np) {
            mls[p] = g_ML[(size_t)(p * B_DIM + b) * T_DIM + t];
            mmax = fmaxf(mmax, mls[p].x);
        }
    }
    float l = 0.f;
    float4 ov = make_float4(0.f, 0.f, 0.f, 0.f);
#pragma unroll 8
    for (int p = 0; p < 8; p++) {
        if (p < np) {
            float wgt = ex2f(mls[p].x - mmax);
            l += mls[p].y * wgt;
            float4 v = *(const float4*)&g_Op[((size_t)(p * B_DIM + b) * T_DIM + t) * H_DIM + c];
            ov.x += v.x * wgt; ov.y += v.y * wgt;
            ov.z += v.z * wgt; ov.w += v.w * wgt;
        }
    }
    float inv = 1.f / l;
    *(float4*)&out[((size_t)b * T_DIM + t) * H_DIM + c] =
        make_float4(ov.x * inv, ov.y * inv, ov.z * inv, ov.w * inv);
}

// ---------------------------------------------------------------------------
extern "C" void kernel_launch(void* const* d_in, const int* in_sizes, int n_in,
                              void* d_out, int out_size)
{
    (void)in_sizes; (void)n_in; (void)out_size;
    const float* x  = (const float*)d_in[0];
    const float* Wq = (const float*)d_in[1];
    const float* Wk = (const float*)d_in[2];
    const float* Wv = (const float*)d_in[3];
    float* out = (float*)d_out;

    splitw_kernel<<<192, 256>>>(Wq, Wk, Wv);

    cudaFuncSetAttribute(proj_kernel,
                         cudaFuncAttributeMaxDynamicSharedMemorySize, PSM_TOTAL);
    proj_kernel<<<128, 256, PSM_TOTAL>>>(x);

    cudaFuncSetAttribute(attn_kernel,
                         cudaFuncAttributeMaxDynamicSharedMemorySize, SM_TOTAL);
    attn_kernel<<<GRID_W, 256, SM_TOTAL>>>();

    combine_kernel<<<1024, 256>>>(out);
}